// round 5
// baseline (speedup 1.0000x reference)
#include <cuda_runtime.h>

// Problem constants (fixed by the reference: N=8192, K=10, M=3)
#define N_ROWS 8192
#define K_DIM  10
#define M_DIM  3

#define TILE_I 32
#define TILE_J 2048
#define THREADS 256

// ---------------------------------------------------------------------------
// Fused kernel:
//   mid[n][m] = max_k( |x[n][k]| + |w1[m][k]| )          (recomputed per block)
//   out[i][j] = max_{m<3}( mid[i][m] + mid[j][m] )
//
// Block tile: 32 rows (i) x 2048 cols (j), 256 threads. Grid = 1024 blocks =
// ONE wave at 8 blocks/SM (no wave transition). Each thread owns 8
// consecutive j columns (24 b-values in registers) and emits one 256-bit
// st.global.v8.f32 per row (sm_100+).
// ---------------------------------------------------------------------------
__global__ __launch_bounds__(THREADS)
void fused_kernel(const float* __restrict__ x,
                  const float* __restrict__ w1,
                  float* __restrict__ out) {
    __shared__ float sw[M_DIM * K_DIM];   // |w1|
    __shared__ float sb[TILE_J * M_DIM];  // mid for j-tile (24 KB)
    __shared__ float sa[TILE_I * M_DIM];  // mid for i-tile

    const int tid = threadIdx.x;
    const int j0 = blockIdx.x * TILE_J;
    const int i0 = blockIdx.y * TILE_I;

    if (tid < M_DIM * K_DIM) sw[tid] = fabsf(w1[tid]);
    __syncthreads();

    // mid for j-tile: 2048 rows, 8 rows per thread
    for (int r = tid; r < TILE_J; r += THREADS) {
        const int n = j0 + r;
        float xa[K_DIM];
#pragma unroll
        for (int k = 0; k < K_DIM; ++k) xa[k] = fabsf(__ldg(&x[n * K_DIM + k]));
#pragma unroll
        for (int m = 0; m < M_DIM; ++m) {
            float v = xa[0] + sw[m * K_DIM + 0];
#pragma unroll
            for (int k = 1; k < K_DIM; ++k)
                v = fmaxf(v, xa[k] + sw[m * K_DIM + k]);
            sb[r * M_DIM + m] = v;
        }
    }

    // mid for i-tile: 32 rows
    if (tid < TILE_I) {
        const int n = i0 + tid;
        float xa[K_DIM];
#pragma unroll
        for (int k = 0; k < K_DIM; ++k) xa[k] = fabsf(__ldg(&x[n * K_DIM + k]));
#pragma unroll
        for (int m = 0; m < M_DIM; ++m) {
            float v = xa[0] + sw[m * K_DIM + 0];
#pragma unroll
            for (int k = 1; k < K_DIM; ++k)
                v = fmaxf(v, xa[k] + sw[m * K_DIM + k]);
            sa[tid * M_DIM + m] = v;
        }
    }
    __syncthreads();

    // Each thread: 8 consecutive j values -> 24 b-components in registers.
    const int jl = tid * 8;  // local j within tile (32B-aligned in the output)
    float bx[8], by[8], bz[8];
#pragma unroll
    for (int q = 0; q < 8; ++q) {
        bx[q] = sb[(jl + q) * M_DIM + 0];
        by[q] = sb[(jl + q) * M_DIM + 1];
        bz[q] = sb[(jl + q) * M_DIM + 2];
    }

    float* optr = out + (long)i0 * N_ROWS + j0 + jl;

#pragma unroll 4
    for (int r = 0; r < TILE_I; ++r) {
        const float a0 = sa[r * M_DIM + 0];
        const float a1 = sa[r * M_DIM + 1];
        const float a2 = sa[r * M_DIM + 2];

        float v[8];
#pragma unroll
        for (int q = 0; q < 8; ++q)
            v[q] = fmaxf(fmaxf(a0 + bx[q], a1 + by[q]), a2 + bz[q]);

        // 256-bit store (sm_100+)
        asm volatile(
            "st.global.v8.f32 [%0], {%1, %2, %3, %4, %5, %6, %7, %8};"
            :: "l"(optr + (long)r * N_ROWS),
               "f"(v[0]), "f"(v[1]), "f"(v[2]), "f"(v[3]),
               "f"(v[4]), "f"(v[5]), "f"(v[6]), "f"(v[7])
            : "memory");
    }
}

// ---------------------------------------------------------------------------
extern "C" void kernel_launch(void* const* d_in, const int* in_sizes, int n_in,
                              void* d_out, int out_size) {
    const float* x  = (const float*)d_in[0];   // (8192, 10)
    const float* w1 = (const float*)d_in[1];   // (3, 10)
    float* out = (float*)d_out;                // (8192, 8192)

    dim3 grid(N_ROWS / TILE_J, N_ROWS / TILE_I);  // (4, 256) = 1024 blocks
    fused_kernel<<<grid, THREADS>>>(x, w1, out);
}

// round 6
// speedup vs baseline: 1.1542x; 1.1542x over previous
#include <cuda_runtime.h>

// Problem constants (fixed by the reference: N=8192, K=10, M=3)
#define N_ROWS 8192
#define K_DIM  10
#define M_DIM  3

#define TILE_I 16
#define TILE_J 1024
#define THREADS 256

#define NT_J   (N_ROWS / TILE_J)   // 8
#define NT_I   (N_ROWS / TILE_I)   // 512
#define N_TILES (NT_J * NT_I)      // 4096
#define NSM    148
#define GRID   (NSM * 8)           // 1184 persistent blocks; 1184 % NT_J == 0
#define MAX_K  4                   // ceil(N_TILES / GRID)

// ---------------------------------------------------------------------------
// Persistent fused kernel.
//   mid[n][m] = max_k( |x[n][k]| + |w1[m][k]| )
//   out[i][j] = max_{m<3}( mid[i][m] + mid[j][m] )
//
// Each block owns tiles {b, b+GRID, b+2*GRID, b+3*GRID}. Since GRID is a
// multiple of NT_J, the j-tile (tj = b % 8) is IDENTICAL for all of them:
// the 12 KB j-mid table and each thread's 12 b-values are computed once.
// All (<=4) i-tile mid sets are computed in the same prologue, so the main
// loop is a pure store stream with zero __syncthreads.
// ---------------------------------------------------------------------------
__global__ __launch_bounds__(THREADS)
void fused_persistent_kernel(const float* __restrict__ x,
                             const float* __restrict__ w1,
                             float* __restrict__ out) {
    __shared__ float sw[M_DIM * K_DIM];          // |w1|
    __shared__ float sb[TILE_J * M_DIM];         // j-tile mids (12 KB)
    __shared__ float sa[MAX_K][TILE_I * M_DIM];  // i-tile mids for all sub-tiles

    const int tid = threadIdx.x;
    const int b   = blockIdx.x;
    const int tj  = b % NT_J;        // constant j-tile for this block
    const int ti0 = b / NT_J;        // first i-tile
    const int j0  = tj * TILE_J;

    if (tid < M_DIM * K_DIM) sw[tid] = fabsf(w1[tid]);
    __syncthreads();

    // ---- prologue: j-tile mids (1024 rows, 4 per thread) ----
    for (int r = tid; r < TILE_J; r += THREADS) {
        const int n = j0 + r;
        float xa[K_DIM];
#pragma unroll
        for (int k = 0; k < K_DIM; ++k) xa[k] = fabsf(__ldg(&x[n * K_DIM + k]));
#pragma unroll
        for (int m = 0; m < M_DIM; ++m) {
            float v = xa[0] + sw[m * K_DIM + 0];
#pragma unroll
            for (int k = 1; k < K_DIM; ++k)
                v = fmaxf(v, xa[k] + sw[m * K_DIM + k]);
            sb[r * M_DIM + m] = v;
        }
    }

    // ---- prologue: i-tile mids for all (<=4) sub-tiles (64 threads) ----
    if (tid < MAX_K * TILE_I) {
        const int k_sub = tid >> 4;          // 0..3
        const int r     = tid & 15;          // row within tile
        const int tile  = b + k_sub * GRID;
        if (tile < N_TILES) {
            const int n = (ti0 + k_sub * (GRID / NT_J)) * TILE_I + r;
            float xa[K_DIM];
#pragma unroll
            for (int k = 0; k < K_DIM; ++k) xa[k] = fabsf(__ldg(&x[n * K_DIM + k]));
#pragma unroll
            for (int m = 0; m < M_DIM; ++m) {
                float v = xa[0] + sw[m * K_DIM + 0];
#pragma unroll
                for (int k = 1; k < K_DIM; ++k)
                    v = fmaxf(v, xa[k] + sw[m * K_DIM + k]);
                sa[k_sub][r * M_DIM + m] = v;
            }
        }
    }
    __syncthreads();

    // ---- per-thread b-values: 4 consecutive j columns, hoisted once ----
    const int jl = tid * 4;
    const float b0x = sb[(jl + 0) * M_DIM + 0], b0y = sb[(jl + 0) * M_DIM + 1], b0z = sb[(jl + 0) * M_DIM + 2];
    const float b1x = sb[(jl + 1) * M_DIM + 0], b1y = sb[(jl + 1) * M_DIM + 1], b1z = sb[(jl + 1) * M_DIM + 2];
    const float b2x = sb[(jl + 2) * M_DIM + 0], b2y = sb[(jl + 2) * M_DIM + 1], b2z = sb[(jl + 2) * M_DIM + 2];
    const float b3x = sb[(jl + 3) * M_DIM + 0], b3y = sb[(jl + 3) * M_DIM + 1], b3z = sb[(jl + 3) * M_DIM + 2];

    const long row_stride4 = N_ROWS / 4;  // in float4 units

    // ---- main loop: pure store stream, no syncs ----
#pragma unroll
    for (int k_sub = 0; k_sub < MAX_K; ++k_sub) {
        const int tile = b + k_sub * GRID;
        if (tile >= N_TILES) break;
        const int i0 = (ti0 + k_sub * (GRID / NT_J)) * TILE_I;

        float4* out4 = reinterpret_cast<float4*>(out + (long)i0 * N_ROWS + j0 + jl);

#pragma unroll 4
        for (int r = 0; r < TILE_I; ++r) {
            const float a0 = sa[k_sub][r * M_DIM + 0];
            const float a1 = sa[k_sub][r * M_DIM + 1];
            const float a2 = sa[k_sub][r * M_DIM + 2];

            float4 v;
            v.x = fmaxf(fmaxf(a0 + b0x, a1 + b0y), a2 + b0z);
            v.y = fmaxf(fmaxf(a0 + b1x, a1 + b1y), a2 + b1z);
            v.z = fmaxf(fmaxf(a0 + b2x, a1 + b2y), a2 + b2z);
            v.w = fmaxf(fmaxf(a0 + b3x, a1 + b3y), a2 + b3z);

            out4[(long)r * row_stride4] = v;
        }
    }
}

// ---------------------------------------------------------------------------
extern "C" void kernel_launch(void* const* d_in, const int* in_sizes, int n_in,
                              void* d_out, int out_size) {
    const float* x  = (const float*)d_in[0];   // (8192, 10)
    const float* w1 = (const float*)d_in[1];   // (3, 10)
    float* out = (float*)d_out;                // (8192, 8192)

    fused_persistent_kernel<<<GRID, THREADS>>>(x, w1, out);
}

// round 8
// speedup vs baseline: 1.6556x; 1.4344x over previous
#include <cuda_runtime.h>

// Problem constants (fixed by the reference: N=8192, K=10, M=3)
#define N_ROWS 8192
#define K_DIM  10
#define M_DIM  3

// Scratch for the (8192 x 3) intermediate — device global (no allocs allowed).
__device__ float g_mid[N_ROWS * M_DIM];

// ---------------------------------------------------------------------------
// Stage 1: mid[n][m] = max_k( |x[n][k]| + |w1[m][k]| )
// ---------------------------------------------------------------------------
__global__ void stage1_kernel(const float* __restrict__ x,
                              const float* __restrict__ w1) {
    __shared__ float sw[M_DIM * K_DIM];
    int tid = threadIdx.x;
    if (tid < M_DIM * K_DIM) sw[tid] = fabsf(w1[tid]);
    __syncthreads();

    int n = blockIdx.x * blockDim.x + tid;
    if (n >= N_ROWS) return;

    float xa[K_DIM];
#pragma unroll
    for (int k = 0; k < K_DIM; ++k) xa[k] = fabsf(x[n * K_DIM + k]);

#pragma unroll
    for (int m = 0; m < M_DIM; ++m) {
        float v = xa[0] + sw[m * K_DIM + 0];
#pragma unroll
        for (int k = 1; k < K_DIM; ++k)
            v = fmaxf(v, xa[k] + sw[m * K_DIM + k]);
        g_mid[n * M_DIM + m] = v;
    }
}

// ---------------------------------------------------------------------------
// Stage 2: out[i][j] = max_{m<3}( mid[i][m] + mid[j][m] )
// Block tile: 32 rows (i) x 512 cols (j), 128 threads. Same per-warp store
// pattern as the proven R1 config (each thread 4 consecutive j -> one
// STG.128 per row, 512B contiguous per warp), but HALF the block duration:
// finer drain granularity at kernel end (drain tail was ~13% of runtime
// with 128KB blocks). 16 blocks/SM resident (2048 threads, 32 regs, 6.4KB).
// ---------------------------------------------------------------------------
#define TILE_I 32
#define TILE_J 512
#define THREADS 128

__global__ __launch_bounds__(THREADS, 16)
void stage2_kernel(float* __restrict__ out) {
    __shared__ float sb[TILE_J * M_DIM];  // 6 KB: mid for j-tile
    __shared__ float sa[TILE_I * M_DIM];  // mid for i-tile

    const int j0 = blockIdx.x * TILE_J;
    const int i0 = blockIdx.y * TILE_I;
    const int tid = threadIdx.x;

    // cooperative stage of mid tiles (coalesced: contiguous in g_mid)
    for (int idx = tid; idx < TILE_J * M_DIM; idx += THREADS)
        sb[idx] = g_mid[j0 * M_DIM + idx];
    for (int idx = tid; idx < TILE_I * M_DIM; idx += THREADS)
        sa[idx] = g_mid[i0 * M_DIM + idx];
    __syncthreads();

    // Each thread: 4 consecutive j values -> 12 b-components in registers.
    const int jl = tid * 4;  // local j within tile
    const float b0x = sb[(jl + 0) * M_DIM + 0], b0y = sb[(jl + 0) * M_DIM + 1], b0z = sb[(jl + 0) * M_DIM + 2];
    const float b1x = sb[(jl + 1) * M_DIM + 0], b1y = sb[(jl + 1) * M_DIM + 1], b1z = sb[(jl + 1) * M_DIM + 2];
    const float b2x = sb[(jl + 2) * M_DIM + 0], b2y = sb[(jl + 2) * M_DIM + 1], b2z = sb[(jl + 2) * M_DIM + 2];
    const float b3x = sb[(jl + 3) * M_DIM + 0], b3y = sb[(jl + 3) * M_DIM + 1], b3z = sb[(jl + 3) * M_DIM + 2];

    float4* out4 = reinterpret_cast<float4*>(out + (long)i0 * N_ROWS + j0 + jl);
    const long row_stride4 = N_ROWS / 4;  // in float4 units

#pragma unroll 4
    for (int r = 0; r < TILE_I; ++r) {
        const float a0 = sa[r * M_DIM + 0];
        const float a1 = sa[r * M_DIM + 1];
        const float a2 = sa[r * M_DIM + 2];

        float4 v;
        v.x = fmaxf(fmaxf(a0 + b0x, a1 + b0y), a2 + b0z);
        v.y = fmaxf(fmaxf(a0 + b1x, a1 + b1y), a2 + b1z);
        v.z = fmaxf(fmaxf(a0 + b2x, a1 + b2y), a2 + b2z);
        v.w = fmaxf(fmaxf(a0 + b3x, a1 + b3y), a2 + b3z);

        out4[(long)r * row_stride4] = v;
    }
}

// ---------------------------------------------------------------------------
extern "C" void kernel_launch(void* const* d_in, const int* in_sizes, int n_in,
                              void* d_out, int out_size) {
    const float* x  = (const float*)d_in[0];   // (8192, 10)
    const float* w1 = (const float*)d_in[1];   // (3, 10)
    float* out = (float*)d_out;                // (8192, 8192)

    stage1_kernel<<<N_ROWS / 256, 256>>>(x, w1);

    dim3 grid(N_ROWS / TILE_J, N_ROWS / TILE_I);  // (16, 256) = 4096 blocks
    stage2_kernel<<<grid, THREADS>>>(out);
}